// round 17
// baseline (speedup 1.0000x reference)
#include <cuda_runtime.h>
#include <cuda_bf16.h>
#include <math.h>
#include <cstdint>

// Problem constants
#define NTOK   16384      // total tokens (B*H*W)
#define NSEQ   4096       // tokens per batch
#define CH     256        // channels F
#define DQK    32         // q/k dim
#define NQKV   320        // 32+32+256
#define KT2    32         // keys per attention tile

typedef unsigned long long u64;

// ---------------- f32x2 packed-FMA helpers (sm_103a) ----------------
__device__ __forceinline__ u64 pk2(float a, float b) {
    u64 r; asm("mov.b64 %0, {%1,%2};" : "=l"(r) : "f"(a), "f"(b)); return r;
}
__device__ __forceinline__ u64 fma2(u64 a, u64 b, u64 c) {
    u64 d; asm("fma.rn.f32x2 %0, %1, %2, %3;" : "=l"(d) : "l"(a), "l"(b), "l"(c)); return d;
}
__device__ __forceinline__ void upk2(u64 v, float& lo, float& hi) {
    asm("mov.b64 {%0,%1}, %2;" : "=f"(lo), "=f"(hi) : "l"(v));
}
__device__ __forceinline__ uint32_t cvt_bf16x2(float lo, float hi) {
    uint32_t r; asm("cvt.rn.bf16x2.f32 %0, %1, %2;" : "=r"(r) : "f"(hi), "f"(lo)); return r;
}
__device__ __forceinline__ uint32_t smem_to_u32(const void* p) {
    uint32_t a;
    asm("{ .reg .u64 tmp; cvta.to.shared.u64 tmp, %1; cvt.u32.u64 %0, tmp; }" : "=r"(a) : "l"(p));
    return a;
}

// ---------------- classic tensor-core ops (baseline PTX, legal at compute_103) ----------------
#define LDMX4(r0, r1, r2, r3, addr) \
    asm volatile("ldmatrix.sync.aligned.m8n8.x4.shared.b16 {%0,%1,%2,%3}, [%4];" \
        : "=r"(r0), "=r"(r1), "=r"(r2), "=r"(r3) : "r"(addr))
#define LDMX4T(r0, r1, r2, r3, addr) \
    asm volatile("ldmatrix.sync.aligned.m8n8.x4.trans.shared.b16 {%0,%1,%2,%3}, [%4];" \
        : "=r"(r0), "=r"(r1), "=r"(r2), "=r"(r3) : "r"(addr))
#define MMA_BF16(c, a0, a1, a2, a3, b0, b1) \
    asm volatile("mma.sync.aligned.m16n8k16.row.col.f32.bf16.bf16.f32 " \
        "{%0,%1,%2,%3}, {%4,%5,%6,%7}, {%8,%9}, {%0,%1,%2,%3};" \
        : "+f"((c)[0]), "+f"((c)[1]), "+f"((c)[2]), "+f"((c)[3]) \
        : "r"(a0), "r"(a1), "r"(a2), "r"(a3), "r"(b0), "r"(b1))

// ---------------- device scratch (no allocations allowed) ----------------
// Referenced ONLY from device code (host-side symbol is the host shadow;
// ATS on GB300 makes passing it as a kernel arg a silent wrong-memory write).
__device__ float g_q[NTOK * DQK];
__device__ float g_k[NTOK * DQK];
__device__ float g_v[NTOK * CH];
__device__ float g_att[NTOK * CH];
__device__ float g_wqkv[CH * NQKV];
__device__ float g_bias[NQKV];
__device__ __align__(16) __nv_bfloat16 g_vb[(size_t)NTOK * CH];  // V bf16 [tok][ch]

// ---------------- prep: concat weights + biases ----------------
__global__ void prep_kernel(const float* __restrict__ Wq, const float* __restrict__ bq,
                            const float* __restrict__ Wk, const float* __restrict__ bk,
                            const float* __restrict__ Wv, const float* __restrict__ bv) {
    int i = blockIdx.x * blockDim.x + threadIdx.x;
    if (i < CH * NQKV) {
        int d = i / NQKV, c = i % NQKV;
        float val;
        if (c < 32)       val = Wq[d * 32 + c];
        else if (c < 64)  val = Wk[d * 32 + (c - 32)];
        else              val = Wv[d * 256 + (c - 64)];
        g_wqkv[i] = val;
    } else if (i < CH * NQKV + NQKV) {
        int c = i - CH * NQKV;
        g_bias[c] = (c < 32) ? bq[c] : (c < 64) ? bk[c - 32] : bv[c - 64];
    }
}

// ---------------- gemm: qkv projection (epilogue also emits V in bf16) ----------------
__global__ __launch_bounds__(256) void gemm_qkv_kernel(const float* __restrict__ X) {
    __shared__ float As[16][68];
    __shared__ float Bs[16][68];
    int t = threadIdx.x;
    int m0 = blockIdx.x * 64;
    int n0 = blockIdx.y * 64;
    int tr = t >> 4, tc = t & 15;
    int arow = t >> 2, aseg = t & 3;
    int brow = t >> 4, bseg = t & 15;

    float acc[4][4];
#pragma unroll
    for (int i = 0; i < 4; i++)
#pragma unroll
        for (int j = 0; j < 4; j++) acc[i][j] = 0.f;

    for (int k0 = 0; k0 < CH; k0 += 16) {
        float4 av = *(const float4*)&X[(m0 + arow) * CH + k0 + aseg * 4];
        float4 bv = *(const float4*)&g_wqkv[(k0 + brow) * NQKV + n0 + bseg * 4];
        __syncthreads();
        As[aseg * 4 + 0][arow] = av.x;
        As[aseg * 4 + 1][arow] = av.y;
        As[aseg * 4 + 2][arow] = av.z;
        As[aseg * 4 + 3][arow] = av.w;
        *(float4*)&Bs[brow][bseg * 4] = bv;
        __syncthreads();
#pragma unroll
        for (int kk = 0; kk < 16; kk++) {
            float4 a = *(const float4*)&As[kk][tr * 4];
            float4 b = *(const float4*)&Bs[kk][tc * 4];
            acc[0][0] += a.x * b.x; acc[0][1] += a.x * b.y; acc[0][2] += a.x * b.z; acc[0][3] += a.x * b.w;
            acc[1][0] += a.y * b.x; acc[1][1] += a.y * b.y; acc[1][2] += a.y * b.z; acc[1][3] += a.y * b.w;
            acc[2][0] += a.z * b.x; acc[2][1] += a.z * b.y; acc[2][2] += a.z * b.z; acc[2][3] += a.z * b.w;
            acc[3][0] += a.w * b.x; acc[3][1] += a.w * b.y; acc[3][2] += a.w * b.z; acc[3][3] += a.w * b.w;
        }
    }

    int c = n0 + tc * 4;
    float b0 = g_bias[c + 0], b1 = g_bias[c + 1], b2 = g_bias[c + 2], b3 = g_bias[c + 3];
#pragma unroll
    for (int i = 0; i < 4; i++) {
        int gr = m0 + tr * 4 + i;
        float4 o;
        o.x = fmaxf(acc[i][0] + b0, 0.f);
        o.y = fmaxf(acc[i][1] + b1, 0.f);
        o.z = fmaxf(acc[i][2] + b2, 0.f);
        o.w = fmaxf(acc[i][3] + b3, 0.f);
        if (c < 32) {
            *(float4*)&g_q[gr * DQK + c] = o;
        } else if (c < 64) {
            *(float4*)&g_k[gr * DQK + (c - 32)] = o;
        } else {
            *(float4*)&g_v[gr * CH + (c - 64)] = o;
            uint2 h;
            h.x = cvt_bf16x2(o.x, o.y);
            h.y = cvt_bf16x2(o.z, o.w);
            *(uint2*)&g_vb[(size_t)gr * CH + (c - 64)] = h;
        }
    }
}

// ---------------- hybrid flash attention (SIMT fp32 QK + mma.sync bf16 PV) ----------------
// CTA: 64 queries x 256 channels, 256 threads (8 warps).
// Warp w: query group qg=w&1 (32 rows), channel group cg=w>>1 (64 cols).
// O accumulates in fp32 mma fragments: c[2 mtiles][8 ntiles][4].
// Scores: thread sq=t>>2 (query), keys kb=(t&3)*8 .. +7 per 32-key tile; exact f32x2 dot.
// exp(s) with NO max subtraction (relu'd q,k bound s well below fp32 overflow).
#define PSTR 40    // ps row stride (bf16): 80B, 16B-aligned, bank-rotating
#define VSTR 280   // vs row stride (bf16): 560B, 16B-aligned, bank-rotating

__global__ __launch_bounds__(256) void attn_kernel() {
    __shared__ float ks[KT2 * 32];                           // 4 KB  (K tile f32)
    __shared__ __align__(16) __nv_bfloat16 vs[KT2 * VSTR];   // 17.5 KB (V tile bf16)
    __shared__ __align__(16) __nv_bfloat16 ps[64 * PSTR];    // 5 KB  (P tile bf16)
    __shared__ float linv_s[64];

    int t = threadIdx.x;
    int lane = t & 31;
    int w = t >> 5;
    int batch = blockIdx.x >> 6;      // 64 q-tiles per batch
    int qt = blockIdx.x & 63;
    int qrow0 = batch * NSEQ + qt * 64;
    int krow0 = batch * NSEQ;

    int sq = t >> 2;                  // score row (query) 0..63
    int kb = (t & 3) * 8;             // score key base within tile

    // q row packed as 16 f32x2
    u64 q2[16];
    {
        const float* qp = g_q + (size_t)(qrow0 + sq) * DQK;
#pragma unroll
        for (int i = 0; i < 8; i++) {
            float4 f = *(const float4*)(qp + i * 4);
            q2[2 * i + 0] = pk2(f.x, f.y);
            q2[2 * i + 1] = pk2(f.z, f.w);
        }
    }

    // mma tile assignment
    int qg = w & 1;                   // query group (32 rows)
    int cg = w >> 1;                  // channel group (64 cols)
    float c[2][8][4];
#pragma unroll
    for (int i = 0; i < 2; i++)
#pragma unroll
        for (int j = 0; j < 8; j++)
#pragma unroll
            for (int k = 0; k < 4; k++) c[i][j][k] = 0.f;

    // ldmatrix lane->address components
    int mat = lane >> 3, mr = lane & 7;
    uint32_t ps_b = smem_to_u32(ps);
    uint32_t vs_b = smem_to_u32(vs);
    // A (P, row-major [m][k]): mat0=(m,k0) mat1=(m+8,k0) mat2=(m,k8) mat3=(m+8,k8)
    uint32_t addrA0 = ps_b + (uint32_t)((qg * 32 + (mat & 1) * 8 + mr) * (PSTR * 2) + ((mat >> 1) * 8) * 2);
    // B (V, row-major [k][n], trans): mat0=(k0,n0) mat1=(k8,n0) mat2=(k0,n8) mat3=(k8,n8)
    uint32_t addrB0 = vs_b + (uint32_t)(((mat & 1) * 8 + mr) * (VSTR * 2) + (cg * 64 + (mat >> 1) * 8) * 2);

    float lpart = 0.f;

#pragma unroll 1
    for (int kt = 0; kt < NSEQ / KT2; kt++) {
        int kr0 = krow0 + kt * KT2;
        // ---- stage K (32x32 f32) + V (32x256 bf16) ----
        {
            int j = t >> 3, ds = t & 7;
            *(float4*)&ks[j * 32 + ds * 4] =
                *(const float4*)&g_k[(size_t)(kr0 + j) * DQK + ds * 4];
        }
#pragma unroll
        for (int rep = 0; rep < 4; rep++) {
            int i = t + rep * 256;
            int row = i >> 5, seg = i & 31;   // 32 segments of 8 bf16 (16B) per row
            *(uint4*)&vs[row * VSTR + seg * 8] =
                *(const uint4*)(g_vb + (size_t)(kr0 + row) * CH + seg * 8);
        }
        __syncthreads();

        // ---- scores + exp + quantize (8 keys per thread) ----
        uint32_t pr[4];
#pragma unroll
        for (int jp = 0; jp < 4; jp++) {
            float pv[2];
#pragma unroll
            for (int h = 0; h < 2; h++) {
                int key = kb + jp * 2 + h;
                const ulonglong2* kp = (const ulonglong2*)(ks + key * 32);
                u64 sa = 0, sb = 0;
#pragma unroll
                for (int dd = 0; dd < 4; dd++) {
                    ulonglong2 k0 = kp[2 * dd + 0];
                    ulonglong2 k1 = kp[2 * dd + 1];
                    sa = fma2(q2[4 * dd + 0], k0.x, sa);
                    sb = fma2(q2[4 * dd + 1], k0.y, sb);
                    sa = fma2(q2[4 * dd + 2], k1.x, sa);
                    sb = fma2(q2[4 * dd + 3], k1.y, sb);
                }
                float a0, a1, b0, b1;
                upk2(sa, a0, a1); upk2(sb, b0, b1);
                pv[h] = __expf((a0 + a1) + (b0 + b1));
            }
            uint32_t v = cvt_bf16x2(pv[0], pv[1]);
            pr[jp] = v;
            __nv_bfloat162 h2 = *(__nv_bfloat162*)&v;
            lpart += __bfloat162float(h2.x) + __bfloat162float(h2.y);
        }
        *(uint4*)&ps[sq * PSTR + kb] = make_uint4(pr[0], pr[1], pr[2], pr[3]);
        __syncthreads();

        // ---- P @ V via mma.sync (per-warp 32q x 64ch, k=32) ----
#pragma unroll
        for (int kk = 0; kk < 2; kk++) {
            uint32_t a[2][4];
#pragma unroll
            for (int mt = 0; mt < 2; mt++)
                LDMX4(a[mt][0], a[mt][1], a[mt][2], a[mt][3],
                      addrA0 + (uint32_t)(mt * 16 * PSTR * 2 + kk * 32));
#pragma unroll
            for (int np = 0; np < 4; np++) {
                uint32_t b0, b1, b2, b3;
                LDMX4T(b0, b1, b2, b3,
                       addrB0 + (uint32_t)(kk * 16 * VSTR * 2 + np * 32));
#pragma unroll
                for (int mt = 0; mt < 2; mt++) {
                    MMA_BF16(c[mt][np * 2 + 0], a[mt][0], a[mt][1], a[mt][2], a[mt][3], b0, b1);
                    MMA_BF16(c[mt][np * 2 + 1], a[mt][0], a[mt][1], a[mt][2], a[mt][3], b2, b3);
                }
            }
        }
        __syncthreads();
    }

    // ---- normalization: l from quantized p (quad-reduce), then scaled writeout ----
    lpart += __shfl_xor_sync(0xffffffffu, lpart, 1);
    lpart += __shfl_xor_sync(0xffffffffu, lpart, 2);
    if ((lane & 3) == 0) linv_s[sq] = 1.f / lpart;
    __syncthreads();

#pragma unroll
    for (int mt = 0; mt < 2; mt++) {
        int r0 = qg * 32 + mt * 16 + (lane >> 2);
        int r1 = r0 + 8;
        float i0 = linv_s[r0], i1 = linv_s[r1];
        int cbase = cg * 64 + (lane & 3) * 2;
#pragma unroll
        for (int nt = 0; nt < 8; nt++) {
            int col = cbase + nt * 8;
            float2 v0 = make_float2(c[mt][nt][0] * i0, c[mt][nt][1] * i0);
            float2 v1 = make_float2(c[mt][nt][2] * i1, c[mt][nt][3] * i1);
            *(float2*)&g_att[(size_t)(qrow0 + r0) * CH + col] = v0;
            *(float2*)&g_att[(size_t)(qrow0 + r1) * CH + col] = v1;
        }
    }
}

// ---------------- gemm: output projection + relu + residual (unchanged) ----------------
__global__ __launch_bounds__(256) void gemm_out_kernel(
    const float* __restrict__ inputs, const float* __restrict__ Wo,
    const float* __restrict__ bo, float* __restrict__ out) {
    __shared__ float As[16][68];
    __shared__ float Bs[16][68];
    int t = threadIdx.x;
    int m0 = blockIdx.x * 64;
    int n0 = blockIdx.y * 64;
    int tr = t >> 4, tc = t & 15;
    int arow = t >> 2, aseg = t & 3;
    int brow = t >> 4, bseg = t & 15;

    float acc[4][4];
#pragma unroll
    for (int i = 0; i < 4; i++)
#pragma unroll
        for (int j = 0; j < 4; j++) acc[i][j] = 0.f;

    for (int k0 = 0; k0 < CH; k0 += 16) {
        float4 av = *(const float4*)&g_att[(m0 + arow) * CH + k0 + aseg * 4];
        float4 bv = *(const float4*)&Wo[(k0 + brow) * CH + n0 + bseg * 4];
        __syncthreads();
        As[aseg * 4 + 0][arow] = av.x;
        As[aseg * 4 + 1][arow] = av.y;
        As[aseg * 4 + 2][arow] = av.z;
        As[aseg * 4 + 3][arow] = av.w;
        *(float4*)&Bs[brow][bseg * 4] = bv;
        __syncthreads();
#pragma unroll
        for (int kk = 0; kk < 16; kk++) {
            float4 a = *(const float4*)&As[kk][tr * 4];
            float4 b = *(const float4*)&Bs[kk][tc * 4];
            acc[0][0] += a.x * b.x; acc[0][1] += a.x * b.y; acc[0][2] += a.x * b.z; acc[0][3] += a.x * b.w;
            acc[1][0] += a.y * b.x; acc[1][1] += a.y * b.y; acc[1][2] += a.y * b.z; acc[1][3] += a.y * b.w;
            acc[2][0] += a.z * b.x; acc[2][1] += a.z * b.y; acc[2][2] += a.z * b.z; acc[2][3] += a.z * b.w;
            acc[3][0] += a.w * b.x; acc[3][1] += a.w * b.y; acc[3][2] += a.w * b.z; acc[3][3] += a.w * b.w;
        }
    }

    int c = n0 + tc * 4;
    float b0 = bo[c + 0], b1 = bo[c + 1], b2 = bo[c + 2], b3 = bo[c + 3];
#pragma unroll
    for (int i = 0; i < 4; i++) {
        int gr = m0 + tr * 4 + i;
        float4 iv = *(const float4*)&inputs[gr * CH + c];
        float4 o;
        o.x = iv.x + fmaxf(acc[i][0] + b0, 0.f);
        o.y = iv.y + fmaxf(acc[i][1] + b1, 0.f);
        o.z = iv.z + fmaxf(acc[i][2] + b2, 0.f);
        o.w = iv.w + fmaxf(acc[i][3] + b3, 0.f);
        *(float4*)&out[gr * CH + c] = o;
    }
}

// ---------------- launch ----------------
extern "C" void kernel_launch(void* const* d_in, const int* in_sizes, int n_in,
                              void* d_out, int out_size) {
    const float* inputs = (const float*)d_in[0];
    const float* Wq = (const float*)d_in[1];
    const float* bq = (const float*)d_in[2];
    const float* Wk = (const float*)d_in[3];
    const float* bk = (const float*)d_in[4];
    const float* Wv = (const float*)d_in[5];
    const float* bv = (const float*)d_in[6];
    const float* Wo = (const float*)d_in[7];
    const float* bo = (const float*)d_in[8];
    float* out = (float*)d_out;

    int prep_elems = CH * NQKV + NQKV;
    prep_kernel<<<(prep_elems + 255) / 256, 256>>>(Wq, bq, Wk, bk, Wv, bv);

    gemm_qkv_kernel<<<dim3(NTOK / 64, NQKV / 64), 256>>>(inputs);

    attn_kernel<<<4 * (NSEQ / 64), 256>>>();

    gemm_out_kernel<<<dim3(NTOK / 64, CH / 64), 256>>>(inputs, Wo, bo, out);
}